// round 5
// baseline (speedup 1.0000x reference)
#include <cuda_runtime.h>

#define BATCH 4096
#define PC 2380

// ---- smem layout (float offsets) ----
#define OFF_WDW2  0      // 432  conv_w pairs [cp][9] (ull)
#define OFF_CB2   432    // 48   conv_b pairs
#define OFF_WPD2  480    // 144  pdw pairs [cp][9]
#define OFF_BPD2  624    // 16
#define OFF_WPF   640    // 16
#define OFF_BPP2  656    // 16   ppw_b pairs
#define OFF_BVP2  672    // 32   vpw_b pairs
#define OFF_VSUM  704    // 32
#define OFF_CODES 736    // 450 ints -> 1186 (pad 1188)
#define OFF_WPP2  1188   // 256  ppw paired-transposed [ci][copair] (ull)
#define OFF_WVP2  1444   // 1024 vpw paired-transposed [ci][copair] (ull)
#define OFF_STAG  2468   // 225*48 = 10800 (aliased: pp2@2468 3600, pd2@6068 3600)
#define OFF_CONV  13268  // 225*48 = 10800 -> 24068
#define OFF_VL1T  24068  // 33*32 = 1056
#define OFF_VL2T  25124  // 1056 -> 26180
#define SMEM_FLOATS 26180
#define SMEM_BYTES  (SMEM_FLOATS * 4)

typedef unsigned long long ull;

__device__ __forceinline__ void ffma2(ull& d, ull a, ull b) {
    asm("fma.rn.f32x2 %0, %1, %2, %0;" : "+l"(d) : "l"(a), "l"(b));
}
__device__ __forceinline__ ull pk2(float x, float y) {
    ull r; asm("mov.b64 %0, {%1, %2};" : "=l"(r) : "f"(x), "f"(y)); return r;
}
__device__ __forceinline__ float2 unpk(ull v) {
    float2 f; asm("mov.b64 {%0, %1}, %2;" : "=f"(f.x), "=f"(f.y) : "l"(v)); return f;
}

// depthwise 3x3, channel-pair packed, pos-major src/dst (stride cstr), one w column
__device__ __forceinline__ void dwconv_pair(const float* __restrict__ src,
                                            float* __restrict__ dst,
                                            const ull* __restrict__ kk,
                                            ull bias, int w, int cstr)
{
    const bool wl = (w > 0), wr = (w < 14);
    const ull k0=kk[0],k1=kk[1],k2=kk[2],k3=kk[3],k4=kk[4],k5=kk[5],k6=kk[6],k7=kk[7],k8=kk[8];
    ull al=0, am=0, ar=0, bl, bm, br;
    bl = wl ? *(const ull*)(src + (w - 1) * cstr) : 0ull;
    bm =      *(const ull*)(src + w * cstr);
    br = wr ? *(const ull*)(src + (w + 1) * cstr) : 0ull;
    #pragma unroll
    for (int h = 0; h < 15; h++) {
        ull cl, cm, cr;
        if (h < 14) {
            const float* r = src + ((h + 1) * 15) * cstr;
            cl = wl ? *(const ull*)(r + (w - 1) * cstr) : 0ull;
            cm =      *(const ull*)(r + w * cstr);
            cr = wr ? *(const ull*)(r + (w + 1) * cstr) : 0ull;
        } else { cl = cm = cr = 0ull; }
        ull acc = bias;
        ffma2(acc, al, k0); ffma2(acc, am, k1); ffma2(acc, ar, k2);
        ffma2(acc, bl, k3); ffma2(acc, bm, k4); ffma2(acc, br, k5);
        ffma2(acc, cl, k6); ffma2(acc, cm, k7); ffma2(acc, cr, k8);
        float2 f = unpk(acc);
        *(float2*)(dst + (h * 15 + w) * cstr) = make_float2(fmaxf(f.x,0.f), fmaxf(f.y,0.f));
        al = bl; am = bm; ar = br;
        bl = cl; bm = cm; br = cr;
    }
}

extern "C" __global__ void __launch_bounds__(256, 2)
patnet_kernel(const float* __restrict__ emb,
              const float* __restrict__ conv_w, const float* __restrict__ conv_b,
              const float* __restrict__ ppw_w,  const float* __restrict__ ppw_b,
              const float* __restrict__ pdw_w,  const float* __restrict__ pdw_b,
              const float* __restrict__ pf_w,
              const float* __restrict__ vpw_w,  const float* __restrict__ vpw_b,
              const float* __restrict__ vl1_w,  const float* __restrict__ vl1_b,
              const float* __restrict__ vl2_w,  const float* __restrict__ vl2_b,
              const float* __restrict__ vf_w,   const float* __restrict__ vf_b,
              const int* __restrict__ sparse,   const int* __restrict__ board,
              float* __restrict__ out)
{
    extern __shared__ float sm[];
    ull*   wdw2u = (ull*)(sm + OFF_WDW2);
    ull*   cb2u  = (ull*)(sm + OFF_CB2);
    ull*   wpd2u = (ull*)(sm + OFF_WPD2);
    ull*   bpd2u = (ull*)(sm + OFF_BPD2);
    float* wpf   = sm + OFF_WPF;
    ull*   bpp2u = (ull*)(sm + OFF_BPP2);
    ull*   bvp2u = (ull*)(sm + OFF_BVP2);
    float* vsum  = sm + OFF_VSUM;
    int*   codes = (int*)(sm + OFF_CODES);
    ull*   wpp2u = (ull*)(sm + OFF_WPP2);
    ull*   wvp2u = (ull*)(sm + OFF_WVP2);
    float* stag  = sm + OFF_STAG;
    float* conv2 = sm + OFF_CONV;
    float* vl1T  = sm + OFF_VL1T;
    float* vl2T  = sm + OFF_VL2T;
    float* pp2   = sm + OFF_STAG;          // 225*16, alias over dead stag
    float* pd2   = sm + OFF_STAG + 3600;   // 225*16

    const int tid  = threadIdx.x;
    const int b    = blockIdx.x;
    const int lane = tid & 31;

    // ---------- P0: pack weights into smem, codes, FC transposes ----------
    for (int i = tid; i < 216; i += 256) {
        int cp = i / 9, tap = i - cp * 9;
        ((float2*)wdw2u)[i] = make_float2(conv_w[(2*cp)*9 + tap], conv_w[(2*cp+1)*9 + tap]);
    }
    for (int i = tid; i < 72; i += 256) {
        int cp = i / 9, tap = i - cp * 9;
        ((float2*)wpd2u)[i] = make_float2(pdw_w[(2*cp)*9 + tap], pdw_w[(2*cp+1)*9 + tap]);
    }
    if (tid < 24) ((float2*)cb2u)[tid]  = make_float2(conv_b[2*tid], conv_b[2*tid+1]);
    if (tid >= 32 && tid < 40) {
        int k = tid - 32;
        ((float2*)bpd2u)[k] = make_float2(pdw_b[2*k], pdw_b[2*k+1]);
        ((float2*)bpp2u)[k] = make_float2(ppw_b[2*k], ppw_b[2*k+1]);
    }
    if (tid >= 64 && tid < 80) {
        int k = tid - 64;
        ((float2*)bvp2u)[k] = make_float2(vpw_b[2*k], vpw_b[2*k+1]);
    }
    if (tid >= 96 && tid < 112) wpf[tid - 96] = pf_w[tid - 96];
    if (tid >= 128 && tid < 160) vsum[tid - 128] = 0.0f;
    for (int i = tid; i < 128; i += 256) {
        int ci = i >> 3, k = i & 7;
        ((float2*)wpp2u)[ci * 8 + k] = make_float2(ppw_w[(2*k)*16 + ci], ppw_w[(2*k+1)*16 + ci]);
    }
    for (int i = tid; i < 512; i += 256) {
        int ci = i >> 4, k = i & 15;
        ((float2*)wvp2u)[ci * 16 + k] = make_float2(vpw_w[(2*k)*32 + ci], vpw_w[(2*k+1)*32 + ci]);
    }
    for (int i = tid; i < 1024; i += 256) {
        int j = i >> 5, ii = i & 31;
        vl1T[ii * 33 + j] = vl1_w[i];
        vl2T[ii * 33 + j] = vl2_w[i];
    }
    for (int i = tid; i < 450; i += 256) {
        int j = i / 225, p = i - j * 225;
        int sp = sparse[b * 2700 + (10 + j) * 225 + p];
        int bd = board[b * 450 + j * 225 + p];
        int c = (bd > 0) ? PC : sp;
        codes[i] = c + j * (PC + 1);
    }
    __syncthreads();

    // ---------- P1: coalesced gather: warp per position ----------
    {
        const int warpid = tid >> 5;
        const int sub = lane >> 4, q = lane & 15;
        for (int p = warpid; p < 225; p += 8) {
            int code = codes[p + sub * 225];
            float4 v = make_float4(0.f, 0.f, 0.f, 0.f);
            if (q < 12) v = *(const float4*)(emb + code * 48 + q * 4);
            float4 u;
            u.x = __shfl_down_sync(0xffffffffu, v.x, 16);
            u.y = __shfl_down_sync(0xffffffffu, v.y, 16);
            u.z = __shfl_down_sync(0xffffffffu, v.z, 16);
            u.w = __shfl_down_sync(0xffffffffu, v.w, 16);
            if (lane < 12)
                *(float4*)&stag[p * 48 + lane * 4] =
                    make_float4(v.x + u.x, v.y + u.y, v.z + u.z, v.w + u.w);
        }
    }
    __syncthreads();

    // ---------- P2: main depthwise 3x3, 24 ch-pairs x 15 w = 360 tasks ----------
    for (int t = tid; t < 360; t += 256) {
        const int w = t / 24, cp = t - w * 24;
        dwconv_pair(stag + 2 * cp, conv2 + 2 * cp, wdw2u + cp * 9, cb2u[cp], w, 48);
    }
    __syncthreads();

    // ---------- P3a: value 1x1 32->32, 4 slots x 8 co per thread (228 live) ----------
    {
        const int cg = tid & 3, sg = tid >> 2;
        const bool live = (sg < 57);
        const int s0 = live ? sg * 4 : 0;
        ull acc[4][4];
        #pragma unroll
        for (int k = 0; k < 4; k++) {
            ull bi = bvp2u[cg * 4 + k];
            acc[0][k] = bi; acc[1][k] = bi; acc[2][k] = bi; acc[3][k] = bi;
        }
        #pragma unroll
        for (int ci0 = 0; ci0 < 32; ci0 += 4) {
            float4 xv[4];
            #pragma unroll
            for (int j = 0; j < 4; j++) {
                int sl = s0 + j; if (sl > 224) sl = 224;
                xv[j] = *(const float4*)&conv2[sl * 48 + 16 + ci0];
            }
            #pragma unroll
            for (int q = 0; q < 4; q++) {
                ulonglong2 wa = ((const ulonglong2*)&wvp2u[(ci0 + q) * 16 + cg * 4])[0];
                ulonglong2 wb = ((const ulonglong2*)&wvp2u[(ci0 + q) * 16 + cg * 4])[1];
                #pragma unroll
                for (int j = 0; j < 4; j++) {
                    float x = (q == 0) ? xv[j].x : (q == 1) ? xv[j].y : (q == 2) ? xv[j].z : xv[j].w;
                    ull xd = pk2(x, x);
                    ffma2(acc[j][0], xd, wa.x);
                    ffma2(acc[j][1], xd, wa.y);
                    ffma2(acc[j][2], xd, wb.x);
                    ffma2(acc[j][3], xd, wb.y);
                }
            }
        }
        float sv[8];
        #pragma unroll
        for (int k = 0; k < 4; k++) {
            float slo = 0.f, shi = 0.f;
            #pragma unroll
            for (int j = 0; j < 4; j++) {
                bool valid = live && (s0 + j <= 224);
                float2 f = unpk(acc[j][k]);
                if (valid) { slo += fmaxf(f.x, 0.f); shi += fmaxf(f.y, 0.f); }
            }
            sv[2*k] = slo; sv[2*k+1] = shi;
        }
        #pragma unroll
        for (int k = 0; k < 8; k++) {
            float s = sv[k];
            s += __shfl_xor_sync(0xffffffffu, s, 4);
            s += __shfl_xor_sync(0xffffffffu, s, 8);
            s += __shfl_xor_sync(0xffffffffu, s, 16);
            if (lane < 4) atomicAdd(&vsum[cg * 8 + k], s);
        }
    }

    // ---------- P3b: policy 1x1 16->16, 4 slots x 8 co per thread (114 threads) ----------
    if (tid < 114) {
        const int cg = tid & 1, sg = tid >> 1;
        const int s0 = sg * 4;
        ull acc[4][4];
        #pragma unroll
        for (int k = 0; k < 4; k++) {
            ull bi = bpp2u[cg * 4 + k];
            acc[0][k] = bi; acc[1][k] = bi; acc[2][k] = bi; acc[3][k] = bi;
        }
        #pragma unroll
        for (int ci0 = 0; ci0 < 16; ci0 += 4) {
            float4 xv[4];
            #pragma unroll
            for (int j = 0; j < 4; j++) {
                int sl = s0 + j; if (sl > 224) sl = 224;
                xv[j] = *(const float4*)&conv2[sl * 48 + ci0];
            }
            #pragma unroll
            for (int q = 0; q < 4; q++) {
                ulonglong2 wa = ((const ulonglong2*)&wpp2u[(ci0 + q) * 8 + cg * 4])[0];
                ulonglong2 wb = ((const ulonglong2*)&wpp2u[(ci0 + q) * 8 + cg * 4])[1];
                #pragma unroll
                for (int j = 0; j < 4; j++) {
                    float x = (q == 0) ? xv[j].x : (q == 1) ? xv[j].y : (q == 2) ? xv[j].z : xv[j].w;
                    ull xd = pk2(x, x);
                    ffma2(acc[j][0], xd, wa.x);
                    ffma2(acc[j][1], xd, wa.y);
                    ffma2(acc[j][2], xd, wb.x);
                    ffma2(acc[j][3], xd, wb.y);
                }
            }
        }
        #pragma unroll
        for (int j = 0; j < 4; j++) {
            int sl = s0 + j;
            if (sl <= 224) {
                #pragma unroll
                for (int k = 0; k < 4; k++) {
                    float2 f = unpk(acc[j][k]);
                    *(float2*)&pp2[sl * 16 + cg * 8 + 2 * k] =
                        make_float2(fmaxf(f.x, 0.f), fmaxf(f.y, 0.f));
                }
            }
        }
    }
    __syncthreads();

    // ---------- P4: policy depthwise (tid<120) | value FC head (warp 7) ----------
    if (tid < 120) {
        const int cp = tid & 7, w = tid >> 3;
        dwconv_pair(pp2 + 2 * cp, pd2 + 2 * cp, wpd2u + cp * 9, bpd2u[cp], w, 16);
    }
    if (tid >= 224) {
        float v = vsum[lane] * (1.0f / 225.0f);
        float h1 = vl1_b[lane];
        #pragma unroll
        for (int i = 0; i < 32; i++)
            h1 += vl1T[i * 33 + lane] * __shfl_sync(0xffffffffu, v, i);
        h1 = fmaxf(h1, 0.0f);
        float h2 = vl2_b[lane];
        #pragma unroll
        for (int i = 0; i < 32; i++)
            h2 += vl2T[i * 33 + lane] * __shfl_sync(0xffffffffu, h1, i);
        h2 = fmaxf(h2, 0.0f);
        #pragma unroll
        for (int j = 0; j < 3; j++) {
            float s = vf_w[j * 32 + lane] * h2;
            s += __shfl_xor_sync(0xffffffffu, s, 1);
            s += __shfl_xor_sync(0xffffffffu, s, 2);
            s += __shfl_xor_sync(0xffffffffu, s, 4);
            s += __shfl_xor_sync(0xffffffffu, s, 8);
            s += __shfl_xor_sync(0xffffffffu, s, 16);
            if (lane == 0) out[b * 3 + j] = s + vf_b[j];
        }
    }
    __syncthreads();

    // ---------- P5: pf 16->1, one slot per thread ----------
    if (tid < 225) {
        const float4* pr = (const float4*)&pd2[tid * 16];
        float4 a = pr[0], c = pr[1], d = pr[2], e = pr[3];
        const float4* wf4 = (const float4*)wpf;
        float4 w0 = wf4[0], w1 = wf4[1], w2 = wf4[2], w3 = wf4[3];
        float acc = a.x*w0.x + a.y*w0.y + a.z*w0.z + a.w*w0.w
                  + c.x*w1.x + c.y*w1.y + c.z*w1.z + c.w*w1.w
                  + d.x*w2.x + d.y*w2.y + d.z*w2.z + d.w*w2.w
                  + e.x*w3.x + e.y*w3.y + e.z*w3.z + e.w*w3.w;
        out[BATCH * 3 + b * 225 + tid] = acc;
    }
}

extern "C" void kernel_launch(void* const* d_in, const int* in_sizes, int n_in,
                              void* d_out, int out_size) {
    (void)in_sizes; (void)n_in; (void)out_size;
    cudaFuncSetAttribute(patnet_kernel,
                         cudaFuncAttributeMaxDynamicSharedMemorySize, SMEM_BYTES);
    patnet_kernel<<<BATCH, 256, SMEM_BYTES>>>(
        (const float*)d_in[0],  (const float*)d_in[1],  (const float*)d_in[2],
        (const float*)d_in[3],  (const float*)d_in[4],  (const float*)d_in[5],
        (const float*)d_in[6],  (const float*)d_in[7],  (const float*)d_in[8],
        (const float*)d_in[9],  (const float*)d_in[10], (const float*)d_in[11],
        (const float*)d_in[12], (const float*)d_in[13], (const float*)d_in[14],
        (const float*)d_in[15], (const int*)d_in[16],   (const int*)d_in[17],
        (float*)d_out);
}